// round 11
// baseline (speedup 1.0000x reference)
#include <cuda_runtime.h>

#define SPATIAL  3136
#define NBW      128
#define SCALE2   0.35355339059327373f   // 2/sqrt(32)

// phase1: 4-row chunks = 112 positions = 56 pairs, 28 16B-lines per channel
#define P1_ROWB   512
#define P1_TEN    (32 * P1_ROWB)
#define P1_BUF    (2 * P1_TEN)
#define P1_SMEM   (3 * P1_BUF)          // 98304
#define P1_LPT    896

__device__ float g_Pp[NBW * 2 * 1024];

typedef unsigned long long ull;

__device__ __forceinline__ void fma2(ull& d, ull a, ull b) {
    asm("fma.rn.f32x2 %0, %1, %2, %0;" : "+l"(d) : "l"(a), "l"(b));
}
__device__ __forceinline__ ull rep2(float x) {
    ull r; asm("mov.b64 %0, {%1, %1};" : "=l"(r) : "f"(x)); return r;
}
__device__ __forceinline__ float lo32(ull x) { return __uint_as_float((unsigned)x); }
__device__ __forceinline__ float hi32(ull x) { return __uint_as_float((unsigned)(x >> 32)); }
__device__ __forceinline__ void cp16(unsigned dst, const void* src) {
    asm volatile("cp.async.cg.shared.global [%0], [%1], 16;" :: "r"(dst), "l"(src));
}

// ---------------------------------------------------------------------------
// Phase 1 (R5 verbatim): partial P = K^T V. grid (128,2), 256 thr, 2 blk/SM.
// ---------------------------------------------------------------------------
__global__ __launch_bounds__(256, 2)
void phase1(const float* __restrict__ K, const float* __restrict__ V) {
    extern __shared__ __align__(16) char sm[];
    const unsigned sm32 = (unsigned)__cvta_generic_to_shared(sm);

    const int tid  = threadIdx.x;
    const int bw   = blockIdx.x;
    const int sl   = blockIdx.y;
    const int c0   = sl * 7;

    const int win  = bw & 1;
    const int head = (bw >> 1) & 7;
    const int tb   = bw >> 4;
    const int base = (tb * 256 + head * 32) * SPATIAL + win * 28;

    const int ti  = tid & 3;
    const int tj  = (tid >> 2) & 7;
    const int wid = tid >> 5;
    const int keyA = ti * 2;
    const int keyB = ti * 2 + 1;

    auto stage = [&](int ch, int buf) {
        const unsigned bufb = sm32 + buf * P1_BUF;
        const int gofs = base + ch * 224;
        #pragma unroll
        for (int it = 0; it < 7; it++) {
            int idx = it * 256 + tid;
            int tensor = (idx >= P1_LPT) ? 1 : 0;
            int rem = idx - tensor * P1_LPT;
            int c = rem / 28;
            int g = rem - c * 28;
            int r = g / 7;
            int w4 = g - r * 7;
            const float* src = (tensor ? V : K) + gofs + c * SPATIAL + r * 56 + w4 * 4;
            int chs = g ^ ((c >> 2) & 7);
            cp16(bufb + tensor * P1_TEN + c * P1_ROWB + chs * 16, src);
        }
        asm volatile("cp.async.commit_group;");
    };

    ull acc[8][4];
    #pragma unroll
    for (int i = 0; i < 8; i++)
        #pragma unroll
        for (int j = 0; j < 4; j++) acc[i][j] = 0ull;

    stage(c0, 0);
    stage(c0 + 1, 1);

    #pragma unroll
    for (int i = 0; i < 7; i++) {
        if (i < 5) {
            stage(c0 + i + 2, (i + 2) % 3);
            asm volatile("cp.async.wait_group 2;");
        } else if (i == 5) {
            asm volatile("cp.async.wait_group 1;");
        } else {
            asm volatile("cp.async.wait_group 0;");
        }
        __syncthreads();

        const char* kB = sm + (i % 3) * P1_BUF;
        const char* vB = kB + P1_TEN;

        auto loadA = [&](int u, ull* ka) {
            const int pr = wid + u * 8;
            const int col = pr >> 1;
            const unsigned off = ((unsigned)(col ^ keyA) << 4) + ((pr & 1) << 3);
            #pragma unroll
            for (int i2 = 0; i2 < 4; i2++)
                ka[i2] = *(const ull*)(kB + (ti * 8 + i2) * P1_ROWB + off);
        };
        auto loadB = [&](int u, ull* kb) {
            const int pr = wid + u * 8;
            const int col = pr >> 1;
            const unsigned off = ((unsigned)(col ^ keyB) << 4) + ((pr & 1) << 3);
            #pragma unroll
            for (int i2 = 0; i2 < 4; i2++)
                kb[i2] = *(const ull*)(kB + (ti * 8 + 4 + i2) * P1_ROWB + off);
        };
        auto loadV = [&](int u, ull* v) {
            const int pr = wid + u * 8;
            const int col = pr >> 1;
            const unsigned off = ((unsigned)(col ^ tj) << 4) + ((pr & 1) << 3);
            #pragma unroll
            for (int j = 0; j < 4; j++)
                v[j] = *(const ull*)(vB + (tj * 4 + j) * P1_ROWB + off);
        };

        ull kkA[4], kkB[4], vv[4], kkA2[4], vv2[4];
        loadA(0, kkA);
        loadV(0, vv);
        #pragma unroll
        for (int u = 0; u < 7; u++) {
            loadB(u, kkB);
            if (u < 6) { loadA(u + 1, kkA2); loadV(u + 1, vv2); }
            #pragma unroll
            for (int i2 = 0; i2 < 4; i2++)
                #pragma unroll
                for (int j = 0; j < 4; j++)
                    fma2(acc[i2][j], kkA[i2], vv[j]);
            #pragma unroll
            for (int i2 = 0; i2 < 4; i2++)
                #pragma unroll
                for (int j = 0; j < 4; j++)
                    fma2(acc[4 + i2][j], kkB[i2], vv[j]);
            if (u < 6) {
                #pragma unroll
                for (int t = 0; t < 4; t++) { kkA[t] = kkA2[t]; vv[t] = vv2[t]; }
            }
        }
        __syncthreads();
    }

    float* red = (float*)sm;
    #pragma unroll
    for (int i2 = 0; i2 < 8; i2++)
        #pragma unroll
        for (int j = 0; j < 4; j++)
            red[wid * 1024 + (ti * 8 + i2) * 32 + tj * 4 + j] =
                lo32(acc[i2][j]) + hi32(acc[i2][j]);
    __syncthreads();

    float* gp = g_Pp + (bw * 2 + sl) * 1024;
    #pragma unroll
    for (int t = 0; t < 4; t++) {
        const int o = tid + t * 256;
        float s = red[o];
        #pragma unroll
        for (int w = 1; w < 8; w++) s += red[w * 1024 + o];
        gp[o] = s;
    }
}

// ---------------------------------------------------------------------------
// Phase 2: out = Q * P. grid (128 bw, 7 chunks of 8 rows), 128 threads.
// Warp w owns c2 block w*8..w*8+7; lane = position-group (8 positions).
// Q read directly from global (L1-served; 4 warps share the stream);
// P is a true all-lane broadcast from smem. No staging, no barriers in loop.
// ---------------------------------------------------------------------------
__global__ __launch_bounds__(128, 5)
void phase2(const float* __restrict__ Q, float* __restrict__ O) {
    __shared__ __align__(16) float ps[1024];

    const int tid = threadIdx.x;
    const int bw  = blockIdx.x;
    const int ck  = blockIdx.y;
    const int win  = bw & 1;
    const int head = (bw >> 1) & 7;
    const int tb   = bw >> 4;
    const int base = (tb * 256 + head * 32) * SPATIAL + win * 28 + ck * 448;

    // P = (partial0 + partial1) * scale  (128 thr x 2 float4 = 1024 floats)
    {
        const float* p0 = g_Pp + bw * 2048;
        #pragma unroll
        for (int t = 0; t < 2; t++) {
            const int i4 = (tid + t * 128) * 4;
            float4 a = *(const float4*)(p0 + i4);
            float4 b = *(const float4*)(p0 + 1024 + i4);
            float4 s;
            s.x = (a.x + b.x) * SCALE2;
            s.y = (a.y + b.y) * SCALE2;
            s.z = (a.z + b.z) * SCALE2;
            s.w = (a.w + b.w) * SCALE2;
            *(float4*)&ps[i4] = s;
        }
    }
    __syncthreads();

    const int lane = tid & 31;           // position group 0..27 (28..31 idle)
    const int w    = tid >> 5;           // c2 block 0..3
    if (lane >= 28) return;

    const int p0g  = lane * 8;           // first position of the 8
    const int r0   = p0g / 28;
    const int off0 = r0 * 56 + (p0g - r0 * 28);
    const int p1g  = p0g + 4;
    const int r1   = p1g / 28;
    const int off1 = r1 * 56 + (p1g - r1 * 28);

    const float* qp = Q + base;

    ull a[4][8];
    #pragma unroll
    for (int p = 0; p < 4; p++)
        #pragma unroll
        for (int j = 0; j < 8; j++) a[p][j] = 0ull;

    #pragma unroll
    for (int c1 = 0; c1 < 32; c1++) {
        const float* qr = qp + c1 * SPATIAL;
        ulonglong2 qa = *(const ulonglong2*)(qr + off0);   // 4 positions
        ulonglong2 qb = *(const ulonglong2*)(qr + off1);   // next 4
        float4 pa = *(const float4*)&ps[c1 * 32 + w * 8];      // broadcast
        float4 pb = *(const float4*)&ps[c1 * 32 + w * 8 + 4];  // broadcast
        const float pv[8] = {pa.x, pa.y, pa.z, pa.w, pb.x, pb.y, pb.z, pb.w};
        #pragma unroll
        for (int j = 0; j < 8; j++) {
            ull pj = rep2(pv[j]);
            fma2(a[0][j], qa.x, pj);
            fma2(a[1][j], qa.y, pj);
            fma2(a[2][j], qb.x, pj);
            fma2(a[3][j], qb.y, pj);
        }
    }

    #pragma unroll
    for (int j = 0; j < 8; j++) {
        const int c2 = w * 8 + j;
        float* ob = O + base + c2 * SPATIAL;
        float4 o4;
        o4.x = lo32(a[0][j]); o4.y = hi32(a[0][j]);
        o4.z = lo32(a[1][j]); o4.w = hi32(a[1][j]);
        *(float4*)(ob + off0) = o4;
        o4.x = lo32(a[2][j]); o4.y = hi32(a[2][j]);
        o4.z = lo32(a[3][j]); o4.w = hi32(a[3][j]);
        *(float4*)(ob + off1) = o4;
    }
}

// ---------------------------------------------------------------------------
extern "C" void kernel_launch(void* const* d_in, const int* in_sizes, int n_in,
                              void* d_out, int out_size) {
    const float* q = (const float*)d_in[0];
    const float* k = (const float*)d_in[1];
    const float* v = (const float*)d_in[2];
    float* out = (float*)d_out;

    cudaFuncSetAttribute(phase1, cudaFuncAttributeMaxDynamicSharedMemorySize, P1_SMEM);

    phase1<<<dim3(NBW, 2), 256, P1_SMEM>>>(k, v);
    phase2<<<dim3(NBW, 7), 128>>>(q, out);
}

// round 12
// speedup vs baseline: 1.2109x; 1.2109x over previous
#include <cuda_runtime.h>

#define SPATIAL  3136
#define NBW      128
#define SCALE2   0.35355339059327373f   // 2/sqrt(32)

// phase1: 4-row chunks = 112 positions = 56 pairs, 28 16B-lines per channel
#define P1_ROWB   512
#define P1_TEN    (32 * P1_ROWB)
#define P1_BUF    (2 * P1_TEN)
#define P1_SMEM   (3 * P1_BUF)          // 98304
#define P1_LPT    896

__device__ float g_Pp[NBW * 2 * 1024];

typedef unsigned long long ull;

__device__ __forceinline__ void fma2(ull& d, ull a, ull b) {
    asm("fma.rn.f32x2 %0, %1, %2, %0;" : "+l"(d) : "l"(a), "l"(b));
}
__device__ __forceinline__ ull rep2(float x) {
    ull r; asm("mov.b64 %0, {%1, %1};" : "=l"(r) : "f"(x)); return r;
}
__device__ __forceinline__ float lo32(ull x) { return __uint_as_float((unsigned)x); }
__device__ __forceinline__ float hi32(ull x) { return __uint_as_float((unsigned)(x >> 32)); }
__device__ __forceinline__ void cp16(unsigned dst, const void* src) {
    asm volatile("cp.async.cg.shared.global [%0], [%1], 16;" :: "r"(dst), "l"(src));
}

// ---------------------------------------------------------------------------
// Phase 1 (R5 verbatim): partial P = K^T V. grid (128,2), 256 thr, 2 blk/SM.
// ---------------------------------------------------------------------------
__global__ __launch_bounds__(256, 2)
void phase1(const float* __restrict__ K, const float* __restrict__ V) {
    extern __shared__ __align__(16) char sm[];
    const unsigned sm32 = (unsigned)__cvta_generic_to_shared(sm);

    const int tid  = threadIdx.x;
    const int bw   = blockIdx.x;
    const int sl   = blockIdx.y;
    const int c0   = sl * 7;

    const int win  = bw & 1;
    const int head = (bw >> 1) & 7;
    const int tb   = bw >> 4;
    const int base = (tb * 256 + head * 32) * SPATIAL + win * 28;

    const int ti  = tid & 3;
    const int tj  = (tid >> 2) & 7;
    const int wid = tid >> 5;
    const int keyA = ti * 2;
    const int keyB = ti * 2 + 1;

    auto stage = [&](int ch, int buf) {
        const unsigned bufb = sm32 + buf * P1_BUF;
        const int gofs = base + ch * 224;
        #pragma unroll
        for (int it = 0; it < 7; it++) {
            int idx = it * 256 + tid;
            int tensor = (idx >= P1_LPT) ? 1 : 0;
            int rem = idx - tensor * P1_LPT;
            int c = rem / 28;
            int g = rem - c * 28;
            int r = g / 7;
            int w4 = g - r * 7;
            const float* src = (tensor ? V : K) + gofs + c * SPATIAL + r * 56 + w4 * 4;
            int chs = g ^ ((c >> 2) & 7);
            cp16(bufb + tensor * P1_TEN + c * P1_ROWB + chs * 16, src);
        }
        asm volatile("cp.async.commit_group;");
    };

    ull acc[8][4];
    #pragma unroll
    for (int i = 0; i < 8; i++)
        #pragma unroll
        for (int j = 0; j < 4; j++) acc[i][j] = 0ull;

    stage(c0, 0);
    stage(c0 + 1, 1);

    #pragma unroll
    for (int i = 0; i < 7; i++) {
        if (i < 5) {
            stage(c0 + i + 2, (i + 2) % 3);
            asm volatile("cp.async.wait_group 2;");
        } else if (i == 5) {
            asm volatile("cp.async.wait_group 1;");
        } else {
            asm volatile("cp.async.wait_group 0;");
        }
        __syncthreads();

        const char* kB = sm + (i % 3) * P1_BUF;
        const char* vB = kB + P1_TEN;

        auto loadA = [&](int u, ull* ka) {
            const int pr = wid + u * 8;
            const int col = pr >> 1;
            const unsigned off = ((unsigned)(col ^ keyA) << 4) + ((pr & 1) << 3);
            #pragma unroll
            for (int i2 = 0; i2 < 4; i2++)
                ka[i2] = *(const ull*)(kB + (ti * 8 + i2) * P1_ROWB + off);
        };
        auto loadB = [&](int u, ull* kb) {
            const int pr = wid + u * 8;
            const int col = pr >> 1;
            const unsigned off = ((unsigned)(col ^ keyB) << 4) + ((pr & 1) << 3);
            #pragma unroll
            for (int i2 = 0; i2 < 4; i2++)
                kb[i2] = *(const ull*)(kB + (ti * 8 + 4 + i2) * P1_ROWB + off);
        };
        auto loadV = [&](int u, ull* v) {
            const int pr = wid + u * 8;
            const int col = pr >> 1;
            const unsigned off = ((unsigned)(col ^ tj) << 4) + ((pr & 1) << 3);
            #pragma unroll
            for (int j = 0; j < 4; j++)
                v[j] = *(const ull*)(vB + (tj * 4 + j) * P1_ROWB + off);
        };

        ull kkA[4], kkB[4], vv[4], kkA2[4], vv2[4];
        loadA(0, kkA);
        loadV(0, vv);
        #pragma unroll
        for (int u = 0; u < 7; u++) {
            loadB(u, kkB);
            if (u < 6) { loadA(u + 1, kkA2); loadV(u + 1, vv2); }
            #pragma unroll
            for (int i2 = 0; i2 < 4; i2++)
                #pragma unroll
                for (int j = 0; j < 4; j++)
                    fma2(acc[i2][j], kkA[i2], vv[j]);
            #pragma unroll
            for (int i2 = 0; i2 < 4; i2++)
                #pragma unroll
                for (int j = 0; j < 4; j++)
                    fma2(acc[4 + i2][j], kkB[i2], vv[j]);
            if (u < 6) {
                #pragma unroll
                for (int t = 0; t < 4; t++) { kkA[t] = kkA2[t]; vv[t] = vv2[t]; }
            }
        }
        __syncthreads();
    }

    float* red = (float*)sm;
    #pragma unroll
    for (int i2 = 0; i2 < 8; i2++)
        #pragma unroll
        for (int j = 0; j < 4; j++)
            red[wid * 1024 + (ti * 8 + i2) * 32 + tj * 4 + j] =
                lo32(acc[i2][j]) + hi32(acc[i2][j]);
    __syncthreads();

    float* gp = g_Pp + (bw * 2 + sl) * 1024;
    #pragma unroll
    for (int t = 0; t < 4; t++) {
        const int o = tid + t * 256;
        float s = red[o];
        #pragma unroll
        for (int w = 1; w < 8; w++) s += red[w * 1024 + o];
        gp[o] = s;
    }
}

// ---------------------------------------------------------------------------
// Phase 2: out = Q * P. grid (128 bw, 14 chunks of 4 rows), 128 threads.
// Small quantum: 14KB Q tile, 16 ull accs (~70 regs) -> 6 blocks/SM.
// Lane map: c2g = lane&3 (8 c2 each), posg spans 8 values/warp (4 pos each)
// -> q loads dedup to 1 wavefront, ps loads ~1 wavefront.
// ---------------------------------------------------------------------------
__global__ __launch_bounds__(128, 6)
void phase2(const float* __restrict__ Q, float* __restrict__ O) {
    __shared__ __align__(16) float qs[32 * 112];
    __shared__ __align__(16) float ps[1024];

    const int tid = threadIdx.x;
    const int bw  = blockIdx.x;
    const int ck  = blockIdx.y;                    // 0..13, 4 rows each
    const int win  = bw & 1;
    const int head = (bw >> 1) & 7;
    const int tb   = bw >> 4;
    const int base = (tb * 256 + head * 32) * SPATIAL + win * 28 + ck * 224;

    // stage Q tile via cp.async: 896 lines / 128 thr = 7 each
    const unsigned qsa = (unsigned)__cvta_generic_to_shared(qs);
    #pragma unroll
    for (int it = 0; it < 7; it++) {
        int idx = it * 128 + tid;                  // 0..895
        int c = idx / 28;
        int g = idx - c * 28;                      // line 0..27
        int r = g / 7;
        int w4 = g - r * 7;
        cp16(qsa + (c * 112 + g * 4) * 4,
             Q + base + c * SPATIAL + r * 56 + w4 * 4);
    }
    asm volatile("cp.async.commit_group;");

    // P = (partial0 + partial1) * scale while Q streams
    {
        const float* p0 = g_Pp + bw * 2048;
        #pragma unroll
        for (int t = 0; t < 2; t++) {
            const int i4 = (tid + t * 128) * 4;
            float4 a = *(const float4*)(p0 + i4);
            float4 b = *(const float4*)(p0 + 1024 + i4);
            float4 s;
            s.x = (a.x + b.x) * SCALE2;
            s.y = (a.y + b.y) * SCALE2;
            s.z = (a.z + b.z) * SCALE2;
            s.w = (a.w + b.w) * SCALE2;
            *(float4*)&ps[i4] = s;
        }
    }

    asm volatile("cp.async.wait_group 0;");
    __syncthreads();

    const int c2g  = tid & 3;                      // 8 c2 each
    const int posg = tid >> 2;                     // 0..31, active < 28
    if (posg >= 28) return;
    const int pbase = posg * 4;                    // 4 positions

    ull a[2][8];
    #pragma unroll
    for (int p = 0; p < 2; p++)
        #pragma unroll
        for (int j = 0; j < 8; j++) a[p][j] = 0ull;

    #pragma unroll
    for (int c1 = 0; c1 < 32; c1++) {
        ulonglong2 q2 = *(const ulonglong2*)&qs[c1 * 112 + pbase];
        float4 pa = *(const float4*)&ps[c1 * 32 + c2g * 8];
        float4 pb = *(const float4*)&ps[c1 * 32 + c2g * 8 + 4];
        const float pv[8] = {pa.x, pa.y, pa.z, pa.w, pb.x, pb.y, pb.z, pb.w};
        #pragma unroll
        for (int j = 0; j < 8; j++) {
            ull pj = rep2(pv[j]);
            fma2(a[0][j], q2.x, pj);
            fma2(a[1][j], q2.y, pj);
        }
    }

    const int rr = pbase / 28;
    const int ww = pbase - rr * 28;
    float* ob = O + base + rr * 56 + ww;
    #pragma unroll
    for (int j = 0; j < 8; j++) {
        const int c2 = c2g * 8 + j;
        float4 o4;
        o4.x = lo32(a[0][j]);
        o4.y = hi32(a[0][j]);
        o4.z = lo32(a[1][j]);
        o4.w = hi32(a[1][j]);
        *(float4*)(ob + c2 * SPATIAL) = o4;
    }
}

// ---------------------------------------------------------------------------
extern "C" void kernel_launch(void* const* d_in, const int* in_sizes, int n_in,
                              void* d_out, int out_size) {
    const float* q = (const float*)d_in[0];
    const float* k = (const float*)d_in[1];
    const float* v = (const float*)d_in[2];
    float* out = (float*)d_out;

    cudaFuncSetAttribute(phase1, cudaFuncAttributeMaxDynamicSharedMemorySize, P1_SMEM);

    phase1<<<dim3(NBW, 2), 256, P1_SMEM>>>(k, v);
    phase2<<<dim3(NBW, 14), 128>>>(q, out);
}